// round 6
// baseline (speedup 1.0000x reference)
#include <cuda_runtime.h>
#include <cuda_bf16.h>
#include <cstdint>
#include <math.h>

// ---------------- problem constants ----------------
#define BB 4
#define TT 1024
#define EE 768
#define HH 12
#define LL 4
#define VV 50257
#define HDIM 64
#define NROWS (BB*TT)          // 4096

typedef __nv_bfloat16 bf16;

// ---------------- scratch (device globals) ----------------
__device__ float g_x  [NROWS*EE];
__device__ float g_att[(size_t)BB*HH*TT*TT];     // raw scores fp32
__device__ float g_nll[NROWS];
__device__ float g_vld[NROWS];

__device__ bf16 g_xn_h [NROWS*EE],    g_xn_l [NROWS*EE];
__device__ bf16 g_qkv_h[NROWS*3*EE],  g_qkv_l[NROWS*3*EE];
__device__ bf16 g_ap_h [(size_t)BB*HH*TT*TT], g_ap_l[(size_t)BB*HH*TT*TT];  // softmax probs
__device__ bf16 g_vT_h [(size_t)BB*HH*HDIM*TT], g_vT_l[(size_t)BB*HH*HDIM*TT];
__device__ bf16 g_y_h  [NROWS*EE],    g_y_l  [NROWS*EE];
__device__ bf16 g_h_h  [NROWS*4*EE],  g_h_l  [NROWS*4*EE];

__device__ bf16 g_wte_h[(size_t)VV*EE],  g_wte_l[(size_t)VV*EE];
__device__ bf16 g_aw_h [LL*3*EE*EE],     g_aw_l [LL*3*EE*EE];
__device__ bf16 g_pw_h [LL*EE*EE],       g_pw_l [LL*EE*EE];
__device__ bf16 g_fw_h [LL*4*EE*EE],     g_fw_l [LL*4*EE*EE];
__device__ bf16 g_mw_h [LL*4*EE*EE],     g_mw_l [LL*4*EE*EE];

// ---------------- helpers ----------------
__device__ __forceinline__ uint32_t pk2(bf16 a, bf16 b){
    __nv_bfloat162 t = __halves2bfloat162(a, b);
    return *reinterpret_cast<uint32_t*>(&t);
}
__device__ __forceinline__ void split1(float v, bf16& h, bf16& l){
    h = __float2bfloat16_rn(v);
    l = __float2bfloat16_rn(v - __bfloat162float(h));
}

// one-shot splitter: fp32[n] -> hi/lo bf16 (n % 4 == 0)
__global__ void split4_k(const float4* __restrict__ in, uint32_t* __restrict__ oh,
                         uint32_t* __restrict__ ol, int n4)
{
    int i = blockIdx.x*256 + threadIdx.x;
    if (i >= n4) return;
    float4 v = in[i];
    bf16 h0,h1,h2,h3,l0,l1,l2,l3;
    split1(v.x,h0,l0); split1(v.y,h1,l1); split1(v.z,h2,l2); split1(v.w,h3,l3);
    oh[2*i] = pk2(h0,h1); oh[2*i+1] = pk2(h2,h3);
    ol[2*i] = pk2(l0,l1); ol[2*i+1] = pk2(l2,l3);
}

// ---------------- GEMM (NT, pre-split bf16x3) ----------------
#define BM 128
#define BN 128
#define BK 32
#define RS 40                   // bf16 per smem row (80B) -> conflict-free ldmatrix
#define OPW (128*RS)            // bf16 per operand per stage
#define STG (4*OPW)             // Ah Al Bh Bl
#define NSTAGE 3
#define SMEMB (NSTAGE*STG*2)    // 122880 bytes

__device__ __forceinline__ void cpa16(uint32_t dst, const bf16* src, int sz){
    asm volatile("cp.async.cg.shared.global [%0], [%1], 16, %2;\n"
                 :: "r"(dst), "l"(src), "r"(sz));
}
__device__ __forceinline__ void ldsm4(uint32_t& r0, uint32_t& r1, uint32_t& r2,
                                      uint32_t& r3, uint32_t a){
    asm volatile("ldmatrix.sync.aligned.m8n8.x4.shared.b16 {%0,%1,%2,%3}, [%4];\n"
                 : "=r"(r0),"=r"(r1),"=r"(r2),"=r"(r3) : "r"(a));
}
__device__ __forceinline__ void ldsm2(uint32_t& r0, uint32_t& r1, uint32_t a){
    asm volatile("ldmatrix.sync.aligned.m8n8.x2.shared.b16 {%0,%1}, [%2];\n"
                 : "=r"(r0),"=r"(r1) : "r"(a));
}
#define MMA_BF16(Cc, A0,A1,A2,A3, B0,B1)                                     \
    asm volatile("mma.sync.aligned.m16n8k16.row.col.f32.bf16.bf16.f32 "      \
        "{%0,%1,%2,%3}, {%4,%5,%6,%7}, {%8,%9}, {%0,%1,%2,%3};\n"            \
        : "+f"(Cc[0]), "+f"(Cc[1]), "+f"(Cc[2]), "+f"(Cc[3])                 \
        : "r"(A0), "r"(A1), "r"(A2), "r"(A3), "r"(B0), "r"(B1));

// MODE: 0 = +bias -> hi/lo         (QKV)
//       1 = +bias, GELU -> hi/lo   (fc)
//       2 = +bias+residual -> fp32 (attnproj / mlp proj)
//       3 = *scale, causal mask -> fp32, skip upper blocks (scores)
//       4 = store hi/lo, K trimmed to diagonal (AV)
//       5 = plain fp32 store       (lm-head)
template<int MODE>
__global__ void __launch_bounds__(256)
gemm_nt(const bf16* __restrict__ Ah, const bf16* __restrict__ Al,
        long sAo, long sAi, int lda,
        const bf16* __restrict__ Bh, const bf16* __restrict__ Bl,
        long sBo, long sBi, int ldb,
        float* __restrict__ Cf, bf16* __restrict__ Ch, bf16* __restrict__ Cl,
        long sCo, long sCi, int ldc,
        const float* __restrict__ bias, const float* __restrict__ Res, int ldr,
        int M, int N, int K, int innerCnt, float scale)
{
    int bn = blockIdx.x, bm = blockIdx.y, bz = blockIdx.z;
    if (MODE == 3 && bn > bm) return;
    int zo = bz / innerCnt, zi = bz - zo*innerCnt;
    long ao = zo*sAo + zi*sAi, bo = zo*sBo + zi*sBi, co = zo*sCo + zi*sCi;

    extern __shared__ bf16 sm[];
    uint32_t smb = (uint32_t)__cvta_generic_to_shared(sm);

    int Keff = (MODE == 4) ? min(K, (bm+1)*BM) : K;
    int KT = Keff / BK;

    int tid = threadIdx.x;
    const bf16* Abh = Ah + ao + (long)bm*BM*lda;
    const bf16* Abl = Al + ao + (long)bm*BM*lda;
    const bf16* Bbh = Bh + bo + (long)bn*BN*ldb;
    const bf16* Bbl = Bl + bo + (long)bn*BN*ldb;
    int nbase = bn*BN;

    int seg = tid & 3;
    int row0 = tid >> 2, row1 = (tid + 256) >> 2;

    // ---- async stage loader ----
    auto load_stage = [&](int s, int kt){
        int k0 = kt*BK;
        uint32_t base = smb + (uint32_t)s*STG*2;
        #pragma unroll
        for (int c = 0; c < 2; c++){
            int row = c ? row1 : row0;
            uint32_t so = (uint32_t)(row*RS + seg*8)*2;
            long go = (long)row*lda + k0 + seg*8;
            cpa16(base + so,            Abh + go, 16);
            cpa16(base + OPW*2 + so,    Abl + go, 16);
            int bsz = (nbase + row < N) ? 16 : 0;
            long gb = (long)row*ldb + k0 + seg*8;
            cpa16(base + 2*OPW*2 + so,  Bbh + gb, bsz);
            cpa16(base + 3*OPW*2 + so,  Bbl + gb, bsz);
        }
    };

    // prologue: stages 0,1  (KT >= 2 for all call sites)
    load_stage(0, 0);
    asm volatile("cp.async.commit_group;\n");
    load_stage(1, 1);
    asm volatile("cp.async.commit_group;\n");

    float c[4][4][4];
    #pragma unroll
    for (int i=0;i<4;i++)
        #pragma unroll
        for (int j=0;j<4;j++){ c[i][j][0]=0.f;c[i][j][1]=0.f;c[i][j][2]=0.f;c[i][j][3]=0.f; }

    int lane = tid & 31, wid = tid >> 5;
    int wm = (wid >> 2) * 64;     // warps 2 x 4, warp tile 64 x 32
    int wn = (wid & 3) * 32;
    int gq = lane >> 2, tg = lane & 3;
    int aR = lane & 15,        aC = (lane >> 4) * 8;     // ldmatrix x4 lane coords
    int bR = lane & 7,         bC = ((lane >> 3) & 1) * 8;

    for (int kt = 0; kt < KT; kt++){
        __syncthreads();                         // stage (kt+2)%3 free to overwrite
        if (kt + 2 < KT) load_stage((kt+2)%NSTAGE, kt+2);
        asm volatile("cp.async.commit_group;\n");  // possibly empty
        asm volatile("cp.async.wait_group 1;\n");
        __syncthreads();                         // publish stage kt%3

        uint32_t base = smb + (uint32_t)(kt % NSTAGE)*STG*2;
        uint32_t baseAh = base,            baseAl = base + OPW*2;
        uint32_t baseBh = base + 2*OPW*2,  baseBl = base + 3*OPW*2;

        #pragma unroll
        for (int ks = 0; ks < 2; ks++){
            int kc0 = ks*16;
            uint32_t ah[4][4], bh[4][2];
            #pragma unroll
            for (int i=0;i<4;i++)
                ldsm4(ah[i][0],ah[i][1],ah[i][2],ah[i][3],
                      baseAh + (uint32_t)((wm + i*16 + aR)*RS + kc0 + aC)*2);
            #pragma unroll
            for (int j=0;j<4;j++)
                ldsm2(bh[j][0],bh[j][1],
                      baseBh + (uint32_t)((wn + j*8 + bR)*RS + kc0 + bC)*2);
            #pragma unroll
            for (int i=0;i<4;i++)
                #pragma unroll
                for (int j=0;j<4;j++)
                    MMA_BF16(c[i][j], ah[i][0],ah[i][1],ah[i][2],ah[i][3], bh[j][0],bh[j][1]);

            uint32_t bl[4][2];
            #pragma unroll
            for (int j=0;j<4;j++)
                ldsm2(bl[j][0],bl[j][1],
                      baseBl + (uint32_t)((wn + j*8 + bR)*RS + kc0 + bC)*2);
            #pragma unroll
            for (int i=0;i<4;i++)
                #pragma unroll
                for (int j=0;j<4;j++)
                    MMA_BF16(c[i][j], ah[i][0],ah[i][1],ah[i][2],ah[i][3], bl[j][0],bl[j][1]);

            uint32_t al[4][4];
            #pragma unroll
            for (int i=0;i<4;i++)
                ldsm4(al[i][0],al[i][1],al[i][2],al[i][3],
                      baseAl + (uint32_t)((wm + i*16 + aR)*RS + kc0 + aC)*2);
            #pragma unroll
            for (int i=0;i<4;i++)
                #pragma unroll
                for (int j=0;j<4;j++)
                    MMA_BF16(c[i][j], al[i][0],al[i][1],al[i][2],al[i][3], bh[j][0],bh[j][1]);
        }
    }

    // ---- epilogue ----
    #pragma unroll
    for (int i=0;i<4;i++){
        int r0 = bm*BM + wm + i*16 + gq;
        #pragma unroll
        for (int j=0;j<4;j++){
            int c0 = nbase + wn + j*8 + tg*2;
            #pragma unroll
            for (int h2=0; h2<2; h2++){
                int rr = r0 + h2*8;
                #pragma unroll
                for (int cc=0; cc<2; cc++){
                    int col = c0 + cc;
                    if (col >= N) continue;
                    float v = c[i][j][h2*2 + cc];
                    long oidx = co + (long)rr*ldc + col;
                    if (MODE == 0){
                        v += bias[col];
                        bf16 h, l; split1(v, h, l);
                        Ch[oidx] = h; Cl[oidx] = l;
                    } else if (MODE == 1){
                        v += bias[col];
                        v = 0.5f*v*(1.f + erff(v*0.70710678118654752f));
                        bf16 h, l; split1(v, h, l);
                        Ch[oidx] = h; Cl[oidx] = l;
                    } else if (MODE == 2){
                        v += bias[col] + Res[(long)rr*ldr + col];
                        Cf[oidx] = v;
                    } else if (MODE == 3){
                        v *= scale; if (col > rr) v = -1e30f;
                        Cf[oidx] = v;
                    } else if (MODE == 4){
                        bf16 h, l; split1(v, h, l);
                        Ch[oidx] = h; Cl[oidx] = l;
                    } else {
                        Cf[oidx] = v;
                    }
                }
            }
        }
    }
}

// ---------------- embedding ----------------
__global__ void embed_k(const int* __restrict__ idx, const float* __restrict__ wte,
                        const float* __restrict__ wpe, float* __restrict__ x)
{
    int i = blockIdx.x*256 + threadIdx.x;
    if (i >= NROWS*EE) return;
    int row = i / EE, col = i - row*EE;
    int t = row & (TT-1);
    x[i] = wte[(long)idx[row]*EE + col] + wpe[(long)t*EE + col];
}

// ---------------- layernorm -> hi/lo bf16 ----------------
__global__ void layernorm_k(const float* __restrict__ x, const float* __restrict__ w,
                            const float* __restrict__ b,
                            bf16* __restrict__ oh, bf16* __restrict__ ol)
{
    int row = blockIdx.x;
    const float* xr = x + (long)row*EE;
    long obase = (long)row*EE;
    int tid = threadIdx.x;
    float v0 = xr[tid], v1 = xr[tid+256], v2 = xr[tid+512];
    float s = v0+v1+v2, q = v0*v0+v1*v1+v2*v2;
    __shared__ float sh1[256], sh2[256];
    sh1[tid]=s; sh2[tid]=q; __syncthreads();
    #pragma unroll
    for (int off=128; off>0; off>>=1){
        if (tid < off){ sh1[tid]+=sh1[tid+off]; sh2[tid]+=sh2[tid+off]; }
        __syncthreads();
    }
    float mean = sh1[0]*(1.f/EE);
    float var  = sh2[0]*(1.f/EE) - mean*mean;
    float rstd = rsqrtf(var + 1e-5f);
    #pragma unroll
    for (int p = 0; p < 3; p++){
        int cidx = tid + p*256;
        float vv = (p==0? v0 : p==1? v1 : v2);
        float val = (vv-mean)*rstd*w[cidx] + b[cidx];
        bf16 h, l; split1(val, h, l);
        oh[obase+cidx] = h; ol[obase+cidx] = l;
    }
}

// ---------------- V transpose (hi & lo) ----------------
__global__ void transpose_v(const bf16* __restrict__ qh, const bf16* __restrict__ ql,
                            bf16* __restrict__ vh, bf16* __restrict__ vl)
{
    int z = blockIdx.y; int b = z/HH, h = z - b*HH;
    int k0 = blockIdx.x * 64;
    __shared__ bf16 th[64][72], tl[64][72];
    const long sbase = ((long)(b*TT + k0))*(3*EE) + 2*EE + h*HDIM;
    int tid = threadIdx.x;
    #pragma unroll
    for (int i=0;i<16;i++){
        int id = tid + i*256;
        int kr = id >> 6, d = id & 63;
        th[kr][d] = qh[sbase + (long)kr*(3*EE) + d];
        tl[kr][d] = ql[sbase + (long)kr*(3*EE) + d];
    }
    __syncthreads();
    long dbase = (long)z*HDIM*TT + k0;
    #pragma unroll
    for (int i=0;i<16;i++){
        int id = tid + i*256;
        int d = id >> 6, kc = id & 63;
        vh[dbase + (long)d*TT + kc] = th[kc][d];
        vl[dbase + (long)d*TT + kc] = tl[kc][d];
    }
}

// ---------------- causal row softmax -> hi/lo probs ----------------
__global__ void softmax_causal(const float* __restrict__ att,
                               bf16* __restrict__ ph, bf16* __restrict__ pl)
{
    int rid = blockIdx.x;
    int z = rid >> 10, q = rid & (TT-1);
    long base = (long)z*TT*TT + (long)q*TT;
    const float* p = att + base;
    int kend = ((q >> 7) + 1) << 7;
    int tid = threadIdx.x;
    float v[4];
    float m = -1e30f;
    #pragma unroll
    for (int i=0;i<4;i++){
        int k = tid + i*256;
        v[i] = (k < kend) ? p[k] : -1e30f;
        m = fmaxf(m, v[i]);
    }
    __shared__ float sh[256];
    sh[tid] = m; __syncthreads();
    #pragma unroll
    for (int off=128; off>0; off>>=1){
        if (tid < off) sh[tid] = fmaxf(sh[tid], sh[tid+off]);
        __syncthreads();
    }
    m = sh[0]; __syncthreads();
    float s = 0.f;
    #pragma unroll
    for (int i=0;i<4;i++){ v[i] = __expf(v[i] - m); s += v[i]; }
    sh[tid] = s; __syncthreads();
    #pragma unroll
    for (int off=128; off>0; off>>=1){
        if (tid < off) sh[tid] += sh[tid+off];
        __syncthreads();
    }
    float inv = 1.f / sh[0];
    #pragma unroll
    for (int i=0;i<4;i++){
        int k = tid + i*256;
        if (k < kend){
            float val = v[i]*inv;
            bf16 h, l; split1(val, h, l);
            ph[base+k] = h; pl[base+k] = l;
        }
    }
}

// ---------------- loss ----------------
__global__ void loss_rows(const float* __restrict__ lg, const int* __restrict__ tgt,
                          float* __restrict__ nll, float* __restrict__ vld)
{
    long row = blockIdx.x;
    const float* p = lg + row*(long)VV;
    int tid = threadIdx.x;
    float m = -3.0e38f, s = 0.f;
    for (int k = tid; k < VV; k += 256){
        float x = p[k];
        if (x > m){ s = s*__expf(m - x) + 1.f; m = x; }
        else s += __expf(x - m);
    }
    __shared__ float sm[256], ss[256];
    sm[tid]=m; ss[tid]=s; __syncthreads();
    #pragma unroll
    for (int off=128; off>0; off>>=1){
        if (tid < off){
            float m2 = sm[tid+off], s2 = ss[tid+off];
            float mm = fmaxf(sm[tid], m2);
            ss[tid] = ss[tid]*__expf(sm[tid]-mm) + s2*__expf(m2-mm);
            sm[tid] = mm;
        }
        __syncthreads();
    }
    if (tid == 0){
        float lse = sm[0] + logf(ss[0]);
        int t = tgt[row];
        if (t != -1){ nll[row] = lse - p[t]; vld[row] = 1.f; }
        else        { nll[row] = 0.f;       vld[row] = 0.f; }
    }
}

__global__ void loss_final(const float* __restrict__ nll, const float* __restrict__ vld,
                           float* __restrict__ out)
{
    int tid = threadIdx.x;
    float a = 0.f, b = 0.f;
    for (int i = tid; i < NROWS; i += 256){ a += nll[i]; b += vld[i]; }
    __shared__ float s1[256], s2[256];
    s1[tid]=a; s2[tid]=b; __syncthreads();
    #pragma unroll
    for (int off=128; off>0; off>>=1){
        if (tid < off){ s1[tid]+=s1[tid+off]; s2[tid]+=s2[tid+off]; }
        __syncthreads();
    }
    if (tid == 0) out[0] = s1[0] / fmaxf(s2[0], 1.f);
}

// ---------------- host ----------------
static void split_arr(const float* src, bf16* h, bf16* l, long n){
    int n4 = (int)(n/4);
    split4_k<<<(n4 + 255)/256, 256>>>((const float4*)src, (uint32_t*)h, (uint32_t*)l, n4);
}

extern "C" void kernel_launch(void* const* d_in, const int* in_sizes, int n_in,
                              void* d_out, int out_size)
{
    const int*   idx     = (const int*)  d_in[0];
    const int*   tgt     = (const int*)  d_in[1];
    const float* wte     = (const float*)d_in[2];
    const float* wpe     = (const float*)d_in[3];
    const float* ln1_w   = (const float*)d_in[4];
    const float* ln1_b   = (const float*)d_in[5];
    const float* attn_w  = (const float*)d_in[6];
    const float* attn_b  = (const float*)d_in[7];
    const float* aproj_w = (const float*)d_in[8];
    const float* aproj_b = (const float*)d_in[9];
    const float* ln2_w   = (const float*)d_in[10];
    const float* ln2_b   = (const float*)d_in[11];
    const float* fc_w    = (const float*)d_in[12];
    const float* fc_b    = (const float*)d_in[13];
    const float* proj_w  = (const float*)d_in[14];
    const float* proj_b  = (const float*)d_in[15];
    const float* lnf_w   = (const float*)d_in[16];
    const float* lnf_b   = (const float*)d_in[17];
    float* out = (float*)d_out;

    float *x, *att, *nll, *vld;
    bf16 *xn_h,*xn_l,*qkv_h,*qkv_l,*ap_h,*ap_l,*vT_h,*vT_l,*y_h,*y_l,*h_h,*h_l;
    bf16 *wte_h,*wte_l,*aw_h,*aw_l,*pw_h,*pw_l,*fw_h,*fw_l,*mw_h,*mw_l;
    cudaGetSymbolAddress((void**)&x,    g_x);
    cudaGetSymbolAddress((void**)&att,  g_att);
    cudaGetSymbolAddress((void**)&nll,  g_nll);
    cudaGetSymbolAddress((void**)&vld,  g_vld);
    cudaGetSymbolAddress((void**)&xn_h, g_xn_h);  cudaGetSymbolAddress((void**)&xn_l, g_xn_l);
    cudaGetSymbolAddress((void**)&qkv_h,g_qkv_h); cudaGetSymbolAddress((void**)&qkv_l,g_qkv_l);
    cudaGetSymbolAddress((void**)&ap_h, g_ap_h);  cudaGetSymbolAddress((void**)&ap_l, g_ap_l);
    cudaGetSymbolAddress((void**)&vT_h, g_vT_h);  cudaGetSymbolAddress((void**)&vT_l, g_vT_l);
    cudaGetSymbolAddress((void**)&y_h,  g_y_h);   cudaGetSymbolAddress((void**)&y_l,  g_y_l);
    cudaGetSymbolAddress((void**)&h_h,  g_h_h);   cudaGetSymbolAddress((void**)&h_l,  g_h_l);
    cudaGetSymbolAddress((void**)&wte_h,g_wte_h); cudaGetSymbolAddress((void**)&wte_l,g_wte_l);
    cudaGetSymbolAddress((void**)&aw_h, g_aw_h);  cudaGetSymbolAddress((void**)&aw_l, g_aw_l);
    cudaGetSymbolAddress((void**)&pw_h, g_pw_h);  cudaGetSymbolAddress((void**)&pw_l, g_pw_l);
    cudaGetSymbolAddress((void**)&fw_h, g_fw_h);  cudaGetSymbolAddress((void**)&fw_l, g_fw_l);
    cudaGetSymbolAddress((void**)&mw_h, g_mw_h);  cudaGetSymbolAddress((void**)&mw_l, g_mw_l);

    cudaFuncSetAttribute(gemm_nt<0>, cudaFuncAttributeMaxDynamicSharedMemorySize, SMEMB);
    cudaFuncSetAttribute(gemm_nt<1>, cudaFuncAttributeMaxDynamicSharedMemorySize, SMEMB);
    cudaFuncSetAttribute(gemm_nt<2>, cudaFuncAttributeMaxDynamicSharedMemorySize, SMEMB);
    cudaFuncSetAttribute(gemm_nt<3>, cudaFuncAttributeMaxDynamicSharedMemorySize, SMEMB);
    cudaFuncSetAttribute(gemm_nt<4>, cudaFuncAttributeMaxDynamicSharedMemorySize, SMEMB);
    cudaFuncSetAttribute(gemm_nt<5>, cudaFuncAttributeMaxDynamicSharedMemorySize, SMEMB);

    // one-shot weight splits
    split_arr(attn_w,  aw_h, aw_l, (long)LL*3*EE*EE);
    split_arr(aproj_w, pw_h, pw_l, (long)LL*EE*EE);
    split_arr(fc_w,    fw_h, fw_l, (long)LL*4*EE*EE);
    split_arr(proj_w,  mw_h, mw_l, (long)LL*4*EE*EE);
    split_arr(wte,     wte_h, wte_l, (long)VV*EE);

    embed_k<<<(NROWS*EE + 255)/256, 256>>>(idx, wte, wpe, x);

    for (int l = 0; l < LL; l++){
        layernorm_k<<<NROWS, 256>>>(x, ln1_w + l*EE, ln1_b + l*EE, xn_h, xn_l);

        // QKV = xn @ attn_w^T + b  -> hi/lo
        gemm_nt<0><<<dim3(3*EE/BN, NROWS/BM, 1), 256, SMEMB>>>(
            xn_h, xn_l, 0, 0, EE,
            aw_h + (long)l*3*EE*EE, aw_l + (long)l*3*EE*EE, 0, 0, EE,
            nullptr, qkv_h, qkv_l, 0, 0, 3*EE,
            attn_b + (long)l*3*EE, nullptr, 0,
            NROWS, 3*EE, EE, 1, 1.f);

        transpose_v<<<dim3(TT/64, BB*HH), 256>>>(qkv_h, qkv_l, vT_h, vT_l);

        // scores = Q K^T / 8 (causal, z = 48)
        gemm_nt<3><<<dim3(TT/BN, TT/BM, BB*HH), 256, SMEMB>>>(
            qkv_h,      qkv_l,      (long)TT*3*EE, HDIM, 3*EE,
            qkv_h + EE, qkv_l + EE, (long)TT*3*EE, HDIM, 3*EE,
            att, nullptr, nullptr, (long)HH*TT*TT, (long)TT*TT, TT,
            nullptr, nullptr, 0,
            TT, TT, HDIM, HH, 0.125f);

        softmax_causal<<<BB*HH*TT, 256>>>(att, ap_h, ap_l);

        // y = P @ V  (K trimmed to diagonal)
        gemm_nt<4><<<dim3(1, TT/BM, BB*HH), 256, SMEMB>>>(
            ap_h, ap_l, (long)HH*TT*TT,   (long)TT*TT,   TT,
            vT_h, vT_l, (long)HH*HDIM*TT, (long)HDIM*TT, TT,
            nullptr, y_h, y_l, (long)TT*EE, HDIM, EE,
            nullptr, nullptr, 0,
            TT, HDIM, TT, HH, 1.f);

        // x += y @ aproj^T + b
        gemm_nt<2><<<dim3(EE/BN, NROWS/BM, 1), 256, SMEMB>>>(
            y_h, y_l, 0, 0, EE,
            pw_h + (long)l*EE*EE, pw_l + (long)l*EE*EE, 0, 0, EE,
            x, nullptr, nullptr, 0, 0, EE,
            aproj_b + (long)l*EE, x, EE,
            NROWS, EE, EE, 1, 1.f);

        layernorm_k<<<NROWS, 256>>>(x, ln2_w + l*EE, ln2_b + l*EE, xn_h, xn_l);

        // h = gelu(xn @ fc^T + b) -> hi/lo
        gemm_nt<1><<<dim3(4*EE/BN, NROWS/BM, 1), 256, SMEMB>>>(
            xn_h, xn_l, 0, 0, EE,
            fw_h + (long)l*4*EE*EE, fw_l + (long)l*4*EE*EE, 0, 0, EE,
            nullptr, h_h, h_l, 0, 0, 4*EE,
            fc_b + (long)l*4*EE, nullptr, 0,
            NROWS, 4*EE, EE, 1, 1.f);

        // x += h @ proj^T + b
        gemm_nt<2><<<dim3(EE/BN, NROWS/BM, 1), 256, SMEMB>>>(
            h_h, h_l, 0, 0, 4*EE,
            mw_h + (long)l*4*EE*EE, mw_l + (long)l*4*EE*EE, 0, 0, 4*EE,
            x, nullptr, nullptr, 0, 0, EE,
            proj_b + (long)l*EE, x, EE,
            NROWS, EE, 4*EE, 1, 1.f);
    }

    layernorm_k<<<NROWS, 256>>>(x, lnf_w, lnf_b, xn_h, xn_l);

    // logits = xn @ wte^T -> d_out
    gemm_nt<5><<<dim3((VV + BN - 1)/BN, NROWS/BM, 1), 256, SMEMB>>>(
        xn_h, xn_l, 0, 0, EE,
        wte_h, wte_l, 0, 0, EE,
        out, nullptr, nullptr, 0, 0, VV,
        nullptr, nullptr, 0,
        NROWS, VV, EE, 1, 1.f);

    long BTV = (long)NROWS * VV;
    if ((long)out_size > BTV){
        loss_rows<<<NROWS, 256>>>(out, tgt, nll, vld);
        loss_final<<<1, 256>>>(nll, vld, out + BTV);
    }
}